// round 1
// baseline (speedup 1.0000x reference)
#include <cuda_runtime.h>
#include <cuda_bf16.h>

// Problem constants (fixed by the reference)
#define NN      10000
#define KNN     32
#define DG      256
#define ODIM    256
#define XSTRIDE 512   // 2*DG

// Scratch: transformed/clipped feature table h[N][512] (group0 cols 0..255, group1 cols 256..511)
__device__ float g_h[NN * XSTRIDE];
// softmax(a1) || softmax(a2)
__device__ float g_fw[2 * ODIM];

// ---------------------------------------------------------------------------
// Kernel 1: fw = softmax(a) for both groups. One block, 256 threads.
// ---------------------------------------------------------------------------
__global__ void fw_kernel(const float* __restrict__ a1, const float* __restrict__ a2) {
    __shared__ float red[256];
    int t = threadIdx.x;
    for (int g = 0; g < 2; ++g) {
        const float* a = g ? a2 : a1;
        float v = a[t];
        red[t] = v; __syncthreads();
        for (int s = 128; s > 0; s >>= 1) {
            if (t < s) red[t] = fmaxf(red[t], red[t + s]);
            __syncthreads();
        }
        float m = red[0]; __syncthreads();
        float e = expf(v - m);
        red[t] = e; __syncthreads();
        for (int s = 128; s > 0; s >>= 1) {
            if (t < s) red[t] += red[t + s];
            __syncthreads();
        }
        float sum = red[0]; __syncthreads();
        g_fw[g * ODIM + t] = e / sum;
    }
}

// ---------------------------------------------------------------------------
// Kernel 2: h[i, g*256+o] = clip(fw[g,o] * sum_d x[i, g*256+d] * W_g[o,d], -1, 1)
// Tiled fp32 GEMM: BM=64, BN=64, BK=16, 256 threads, 4x4 micro-tile per thread.
// Grid: (ceil(N/64), 256/64, 2)
// ---------------------------------------------------------------------------
#define BM 64
#define BN 64
#define BK 16

__global__ __launch_bounds__(256)
void gemm_kernel(const float* __restrict__ x,
                 const float* __restrict__ W1,
                 const float* __restrict__ W2) {
    const int g  = blockIdx.z;
    const float* __restrict__ W = g ? W2 : W1;
    const int i0 = blockIdx.x * BM;
    const int o0 = blockIdx.y * BN;
    const int xbase = g * DG;

    __shared__ float As[BK][BM + 1];
    __shared__ float Bs[BK][BN + 1];

    const int t    = threadIdx.x;
    const int row  = t >> 2;   // 0..63
    const int quad = t & 3;    // 0..3
    const int tx   = t & 15;   // 0..15 (n)
    const int ty   = t >> 4;   // 0..15 (m)

    float acc[4][4];
    #pragma unroll
    for (int m = 0; m < 4; ++m)
        #pragma unroll
        for (int n = 0; n < 4; ++n) acc[m][n] = 0.f;

    for (int k0 = 0; k0 < DG; k0 += BK) {
        // Load A tile (x): 64 rows x 16 k, one float4 per thread
        {
            int gi = i0 + row;
            float4 av = make_float4(0.f, 0.f, 0.f, 0.f);
            if (gi < NN)
                av = *(const float4*)&x[(size_t)gi * XSTRIDE + xbase + k0 + quad * 4];
            As[quad * 4 + 0][row] = av.x;
            As[quad * 4 + 1][row] = av.y;
            As[quad * 4 + 2][row] = av.z;
            As[quad * 4 + 3][row] = av.w;
        }
        // Load B tile (W): 64 outputs x 16 k
        {
            float4 bv = *(const float4*)&W[(size_t)(o0 + row) * DG + k0 + quad * 4];
            Bs[quad * 4 + 0][row] = bv.x;
            Bs[quad * 4 + 1][row] = bv.y;
            Bs[quad * 4 + 2][row] = bv.z;
            Bs[quad * 4 + 3][row] = bv.w;
        }
        __syncthreads();

        #pragma unroll
        for (int k = 0; k < BK; ++k) {
            float ra[4], rb[4];
            #pragma unroll
            for (int m = 0; m < 4; ++m) ra[m] = As[k][ty * 4 + m];
            #pragma unroll
            for (int n = 0; n < 4; ++n) rb[n] = Bs[k][tx * 4 + n];
            #pragma unroll
            for (int m = 0; m < 4; ++m)
                #pragma unroll
                for (int n = 0; n < 4; ++n)
                    acc[m][n] = fmaf(ra[m], rb[n], acc[m][n]);
        }
        __syncthreads();
    }

    // Epilogue: scale by fw, hardtanh clip, store to scratch table
    #pragma unroll
    for (int m = 0; m < 4; ++m) {
        int gi = i0 + ty * 4 + m;
        if (gi >= NN) continue;
        #pragma unroll
        for (int n = 0; n < 4; ++n) {
            int o = o0 + tx * 4 + n;
            float v = acc[m][n] * g_fw[g * ODIM + o];
            v = fminf(1.0f, fmaxf(-1.0f, v));
            g_h[(size_t)gi * XSTRIDE + g * DG + o] = v;
        }
    }
}

// ---------------------------------------------------------------------------
// Kernel 3: attention. One block = one (node, group). 256 threads.
//  - stage 32 neighbor rows (1KB each) into SMEM (single L2 pass)
//  - squared-distance scores (warp-parallel), softmax over K=32
//  - weighted aggregate, write final output
// ---------------------------------------------------------------------------
__global__ __launch_bounds__(256)
void attn_kernel(const int* __restrict__ graph, float* __restrict__ out) {
    const int i = blockIdx.x;
    const int g = blockIdx.y;

    __shared__ float nb[KNN][DG];   // 32KB
    __shared__ float ov[DG];
    __shared__ float score[KNN];
    __shared__ int   idxs[KNN];

    const int t = threadIdx.x;
    if (t < KNN) idxs[t] = graph[(size_t)i * KNN + t];
    ov[t] = g_h[(size_t)i * XSTRIDE + g * DG + t];
    __syncthreads();

    // Gather neighbors: 32 rows x 64 float4 = 2048 float4; 8 per thread
    #pragma unroll
    for (int r = 0; r < 8; ++r) {
        int lin = r * 256 + t;       // 0..2047
        int j   = lin >> 6;          // neighbor index
        int q   = lin & 63;          // float4 within row
        float4 v = *(const float4*)&g_h[(size_t)idxs[j] * XSTRIDE + g * DG + q * 4];
        *(float4*)&nb[j][q * 4] = v;
    }
    __syncthreads();

    // Scores: warp w handles neighbors w, w+8, w+16, w+24
    const int lane = t & 31;
    const int w    = t >> 5;
    #pragma unroll
    for (int jj = 0; jj < 4; ++jj) {
        int j = w + jj * 8;
        float s = 0.f;
        #pragma unroll
        for (int d = lane; d < DG; d += 32) {
            float diff = ov[d] - nb[j][d];
            s = fmaf(diff, diff, s);
        }
        #pragma unroll
        for (int off = 16; off; off >>= 1) s += __shfl_xor_sync(0xffffffffu, s, off);
        if (lane == 0) score[j] = -s;
    }
    __syncthreads();

    // Softmax over 32 scores in warp 0
    if (w == 0) {
        float s = score[lane];
        float m = s;
        #pragma unroll
        for (int off = 16; off; off >>= 1) m = fmaxf(m, __shfl_xor_sync(0xffffffffu, m, off));
        float e = expf(s - m);
        float sum = e;
        #pragma unroll
        for (int off = 16; off; off >>= 1) sum += __shfl_xor_sync(0xffffffffu, sum, off);
        score[lane] = e / sum;
    }
    __syncthreads();

    // Aggregate: out[i, g*256 + t] = sum_j att[j] * nb[j][t]
    float acc = 0.f;
    #pragma unroll
    for (int j = 0; j < KNN; ++j)
        acc = fmaf(score[j], nb[j][t], acc);
    out[(size_t)i * XSTRIDE + g * DG + t] = acc;
}

// ---------------------------------------------------------------------------
// Launch
// ---------------------------------------------------------------------------
extern "C" void kernel_launch(void* const* d_in, const int* in_sizes, int n_in,
                              void* d_out, int out_size) {
    const float* x     = (const float*)d_in[0];
    const float* W1    = (const float*)d_in[1];
    const float* a1    = (const float*)d_in[2];
    const float* W2    = (const float*)d_in[3];
    const float* a2    = (const float*)d_in[4];
    const int*   graph = (const int*)d_in[5];
    float* out = (float*)d_out;

    fw_kernel<<<1, 256>>>(a1, a2);

    dim3 ggrid((NN + BM - 1) / BM, ODIM / BN, 2);
    gemm_kernel<<<ggrid, 256>>>(x, W1, W2);

    dim3 agrid(NN, 2);
    attn_kernel<<<agrid, 256>>>(graph, out);
}

// round 2
// speedup vs baseline: 1.3310x; 1.3310x over previous
#include <cuda_runtime.h>
#include <cuda_bf16.h>

// Problem constants (fixed by the reference)
#define NN      10000
#define KNN     32
#define DG      256
#define ODIM    256
#define XSTRIDE 512   // 2*DG

// Scratch: transformed/clipped feature table h[N][512]
__device__ float g_h[NN * XSTRIDE];

// ---------------------------------------------------------------------------
// GEMM: h[i, g*256+o] = clip(fw_g[o] * sum_d x[i, g*256+d] * W_g[o,d], -1, 1)
// 128x128x8 tile, 256 threads, 8x8 micro-tile, double-buffered SMEM,
// fw = softmax(a) computed in-block (fused, removes separate kernel).
// Grid: (79, 2, 2)  [row tiles, col tiles, group]
// ---------------------------------------------------------------------------
#define BM 128
#define BN 128
#define BK 8
#define SPAD 4

__global__ __launch_bounds__(256)
void gemm_kernel(const float* __restrict__ x,
                 const float* __restrict__ W1, const float* __restrict__ a1,
                 const float* __restrict__ W2, const float* __restrict__ a2) {
    const int g  = blockIdx.z;
    const float* __restrict__ W = g ? W2 : W1;
    const float* __restrict__ a = g ? a2 : a1;
    const int i0 = blockIdx.x * BM;
    const int o0 = blockIdx.y * BN;

    __shared__ float As[2][BK][BM + SPAD];
    __shared__ float Bs[2][BK][BN + SPAD];
    __shared__ float red[256];
    __shared__ float ea[256];

    const int t  = threadIdx.x;
    const int tx = t & 15;   // n-dim (8 cols each)
    const int ty = t >> 4;   // m-dim (8 rows each)

    // ---- fused fw = softmax(a) ----
    float av_ = a[t];
    red[t] = av_; __syncthreads();
    #pragma unroll
    for (int s = 128; s > 0; s >>= 1) {
        if (t < s) red[t] = fmaxf(red[t], red[t + s]);
        __syncthreads();
    }
    float amax = red[0]; __syncthreads();
    float e = expf(av_ - amax);
    ea[t] = e; red[t] = e; __syncthreads();
    #pragma unroll
    for (int s = 128; s > 0; s >>= 1) {
        if (t < s) red[t] += red[t + s];
        __syncthreads();
    }
    float esum = red[0]; __syncthreads();
    float fwv[8];
    #pragma unroll
    for (int nn = 0; nn < 8; ++nn)
        fwv[nn] = ea[o0 + tx * 8 + nn] / esum;

    // ---- main loop ----
    const int ar = t >> 1;       // 0..127 row within tile
    const int ac = t & 1;        // 0..1 (float4 within 8-k chunk)
    const bool arow_ok = (i0 + ar) < NN;
    const float* __restrict__ xrow = x + (size_t)(i0 + ar) * XSTRIDE + g * DG + ac * 4;
    const float* __restrict__ wrow = W + (size_t)(o0 + ar) * DG + ac * 4;

    float acc[8][8];
    #pragma unroll
    for (int m = 0; m < 8; ++m)
        #pragma unroll
        for (int n = 0; n < 8; ++n) acc[m][n] = 0.f;

    // prologue: stage 0
    {
        float4 avec = make_float4(0.f, 0.f, 0.f, 0.f);
        if (arow_ok) avec = *(const float4*)xrow;
        float4 bvec = *(const float4*)wrow;
        As[0][ac * 4 + 0][ar] = avec.x; As[0][ac * 4 + 1][ar] = avec.y;
        As[0][ac * 4 + 2][ar] = avec.z; As[0][ac * 4 + 3][ar] = avec.w;
        Bs[0][ac * 4 + 0][ar] = bvec.x; Bs[0][ac * 4 + 1][ar] = bvec.y;
        Bs[0][ac * 4 + 2][ar] = bvec.z; Bs[0][ac * 4 + 3][ar] = bvec.w;
    }
    __syncthreads();

    int buf = 0;
    for (int k0 = 0; k0 < DG; k0 += BK) {
        const bool has_next = (k0 + BK) < DG;
        float4 avec = make_float4(0.f, 0.f, 0.f, 0.f), bvec;
        if (has_next) {
            if (arow_ok) avec = *(const float4*)(xrow + k0 + BK);
            bvec = *(const float4*)(wrow + k0 + BK);
        }

        #pragma unroll
        for (int k = 0; k < BK; ++k) {
            float4 a0 = *(const float4*)&As[buf][k][ty * 8];
            float4 a1v = *(const float4*)&As[buf][k][ty * 8 + 4];
            float4 b0 = *(const float4*)&Bs[buf][k][tx * 8];
            float4 b1 = *(const float4*)&Bs[buf][k][tx * 8 + 4];
            float ra[8] = {a0.x, a0.y, a0.z, a0.w, a1v.x, a1v.y, a1v.z, a1v.w};
            float rb[8] = {b0.x, b0.y, b0.z, b0.w, b1.x, b1.y, b1.z, b1.w};
            #pragma unroll
            for (int m = 0; m < 8; ++m)
                #pragma unroll
                for (int n = 0; n < 8; ++n)
                    acc[m][n] = fmaf(ra[m], rb[n], acc[m][n]);
        }

        if (has_next) {
            int nb = buf ^ 1;
            As[nb][ac * 4 + 0][ar] = avec.x; As[nb][ac * 4 + 1][ar] = avec.y;
            As[nb][ac * 4 + 2][ar] = avec.z; As[nb][ac * 4 + 3][ar] = avec.w;
            Bs[nb][ac * 4 + 0][ar] = bvec.x; Bs[nb][ac * 4 + 1][ar] = bvec.y;
            Bs[nb][ac * 4 + 2][ar] = bvec.z; Bs[nb][ac * 4 + 3][ar] = bvec.w;
        }
        __syncthreads();
        buf ^= 1;
    }

    // ---- epilogue: scale by fw, clip, store ----
    #pragma unroll
    for (int m = 0; m < 8; ++m) {
        int gi = i0 + ty * 8 + m;
        if (gi >= NN) continue;
        float4 v0, v1;
        v0.x = fminf(1.f, fmaxf(-1.f, acc[m][0] * fwv[0]));
        v0.y = fminf(1.f, fmaxf(-1.f, acc[m][1] * fwv[1]));
        v0.z = fminf(1.f, fmaxf(-1.f, acc[m][2] * fwv[2]));
        v0.w = fminf(1.f, fmaxf(-1.f, acc[m][3] * fwv[3]));
        v1.x = fminf(1.f, fmaxf(-1.f, acc[m][4] * fwv[4]));
        v1.y = fminf(1.f, fmaxf(-1.f, acc[m][5] * fwv[5]));
        v1.z = fminf(1.f, fmaxf(-1.f, acc[m][6] * fwv[6]));
        v1.w = fminf(1.f, fmaxf(-1.f, acc[m][7] * fwv[7]));
        float* dst = &g_h[(size_t)gi * XSTRIDE + g * DG + o0 + tx * 8];
        *(float4*)dst = v0;
        *(float4*)(dst + 4) = v1;
    }
}

// ---------------------------------------------------------------------------
// Attention: one block per (node, group), 256 threads, neighbors held in
// REGISTERS (no SMEM tile). Thread t owns columns q*4..q*4+3 (q = t&63) of
// 8 neighbors j = 4r + (t>>6).
// ---------------------------------------------------------------------------
__global__ __launch_bounds__(256)
void attn_kernel(const int* __restrict__ graph, float* __restrict__ out) {
    const int i = blockIdx.x;
    const int g = blockIdx.y;

    __shared__ int   idxs[KNN];
    __shared__ float part[2 * KNN];
    __shared__ float score[KNN];
    __shared__ float4 agg[4][64];

    const int t = threadIdx.x;
    if (t < KNN) idxs[t] = graph[(size_t)i * KNN + t];
    __syncthreads();

    const int q    = t & 63;
    const int jb   = t >> 6;
    const int w    = t >> 5;
    const int lane = t & 31;

    const float* __restrict__ base = g_h + g * DG + q * 4;
    float4 ov = *(const float4*)(base + (size_t)i * XSTRIDE);

    // gather 8 neighbor chunks into registers (MLP=8)
    float4 nbv[8];
    #pragma unroll
    for (int r = 0; r < 8; ++r)
        nbv[r] = *(const float4*)(base + (size_t)idxs[4 * r + jb] * XSTRIDE);

    // squared-distance partials -> warp reduce -> 2 partials per j
    #pragma unroll
    for (int r = 0; r < 8; ++r) {
        float dx = ov.x - nbv[r].x, dy = ov.y - nbv[r].y;
        float dz = ov.z - nbv[r].z, dw = ov.w - nbv[r].w;
        float s = dx * dx + dy * dy + dz * dz + dw * dw;
        #pragma unroll
        for (int off = 16; off; off >>= 1) s += __shfl_xor_sync(0xffffffffu, s, off);
        if (lane == 0) part[(4 * r + jb) * 2 + (w & 1)] = s;
    }
    __syncthreads();

    // softmax over 32 scores (warp 0)
    if (t < KNN) {
        float s = -(part[2 * t] + part[2 * t + 1]);
        float m = s;
        #pragma unroll
        for (int off = 16; off; off >>= 1) m = fmaxf(m, __shfl_xor_sync(0xffffffffu, m, off));
        float e = expf(s - m);
        float sum = e;
        #pragma unroll
        for (int off = 16; off; off >>= 1) sum += __shfl_xor_sync(0xffffffffu, sum, off);
        score[t] = e / sum;
    }
    __syncthreads();

    // weighted aggregate from registers
    float4 acc = make_float4(0.f, 0.f, 0.f, 0.f);
    #pragma unroll
    for (int r = 0; r < 8; ++r) {
        float wt = score[4 * r + jb];
        acc.x = fmaf(wt, nbv[r].x, acc.x);
        acc.y = fmaf(wt, nbv[r].y, acc.y);
        acc.z = fmaf(wt, nbv[r].z, acc.z);
        acc.w = fmaf(wt, nbv[r].w, acc.w);
    }
    agg[jb][q] = acc;
    __syncthreads();

    // final cross-thread reduce (4 partials per column group) + store
    if (t < 64) {
        float4 s0 = agg[0][t], s1 = agg[1][t], s2 = agg[2][t], s3 = agg[3][t];
        float4 o;
        o.x = (s0.x + s1.x) + (s2.x + s3.x);
        o.y = (s0.y + s1.y) + (s2.y + s3.y);
        o.z = (s0.z + s1.z) + (s2.z + s3.z);
        o.w = (s0.w + s1.w) + (s2.w + s3.w);
        *(float4*)&out[(size_t)i * XSTRIDE + g * DG + t * 4] = o;
    }
}

// ---------------------------------------------------------------------------
// Launch
// ---------------------------------------------------------------------------
extern "C" void kernel_launch(void* const* d_in, const int* in_sizes, int n_in,
                              void* d_out, int out_size) {
    const float* x     = (const float*)d_in[0];
    const float* W1    = (const float*)d_in[1];
    const float* a1    = (const float*)d_in[2];
    const float* W2    = (const float*)d_in[3];
    const float* a2    = (const float*)d_in[4];
    const int*   graph = (const int*)d_in[5];
    float* out = (float*)d_out;

    dim3 ggrid((NN + BM - 1) / BM, ODIM / BN, 2);
    gemm_kernel<<<ggrid, 256>>>(x, W1, a1, W2, a2);

    dim3 agrid(NN, 2);
    attn_kernel<<<agrid, 256>>>(graph, out);
}

// round 3
// speedup vs baseline: 1.3414x; 1.0079x over previous
#include <cuda_runtime.h>
#include <cuda_bf16.h>

// Problem constants (fixed by the reference)
#define NN      10000
#define KNN     32
#define DG      256
#define ODIM    256
#define XSTRIDE 512   // 2*DG

// Scratch: transformed/clipped feature table h[N][512]
__device__ float g_h[NN * XSTRIDE];

// ---- packed f32x2 helpers (dual-lane fp32 FMA, sm_100+) ----
__device__ __forceinline__ unsigned long long pack2(float v) {
    unsigned long long r;
    asm("mov.b64 %0, {%1, %1};" : "=l"(r) : "f"(v));
    return r;
}
__device__ __forceinline__ void ffma2(unsigned long long& d,
                                      unsigned long long a,
                                      unsigned long long b) {
    asm("fma.rn.f32x2 %0, %1, %2, %3;" : "=l"(d) : "l"(a), "l"(b), "l"(d));
}
__device__ __forceinline__ float2 unpack2(unsigned long long v) {
    float2 f;
    asm("mov.b64 {%0, %1}, %2;" : "=f"(f.x), "=f"(f.y) : "l"(v));
    return f;
}

// ---------------------------------------------------------------------------
// GEMM: h[i, g*256+o] = clip(fw_g[o] * sum_d x[i, g*256+d] * W_g[o,d], -1, 1)
// 128x128x8 tile, 256 threads, 8x8 micro-tile via fma.rn.f32x2 (acc packed
// along n), double-buffered SMEM, fused softmax(a).
// ---------------------------------------------------------------------------
#define BM 128
#define BN 128
#define BK 8
#define SPAD 4

__global__ __launch_bounds__(256)
void gemm_kernel(const float* __restrict__ x,
                 const float* __restrict__ W1, const float* __restrict__ a1,
                 const float* __restrict__ W2, const float* __restrict__ a2) {
    const int g  = blockIdx.z;
    const float* __restrict__ W = g ? W2 : W1;
    const float* __restrict__ a = g ? a2 : a1;
    const int i0 = blockIdx.x * BM;
    const int o0 = blockIdx.y * BN;

    __shared__ __align__(16) float As[2][BK][BM + SPAD];
    __shared__ __align__(16) float Bs[2][BK][BN + SPAD];
    __shared__ float red[256];
    __shared__ float ea[256];

    const int t  = threadIdx.x;
    const int tx = t & 15;   // n-dim (8 cols each)
    const int ty = t >> 4;   // m-dim (8 rows each)

    // ---- fused fw = softmax(a) ----
    float av_ = a[t];
    red[t] = av_; __syncthreads();
    #pragma unroll
    for (int s = 128; s > 0; s >>= 1) {
        if (t < s) red[t] = fmaxf(red[t], red[t + s]);
        __syncthreads();
    }
    float amax = red[0]; __syncthreads();
    float e = expf(av_ - amax);
    ea[t] = e; red[t] = e; __syncthreads();
    #pragma unroll
    for (int s = 128; s > 0; s >>= 1) {
        if (t < s) red[t] += red[t + s];
        __syncthreads();
    }
    float esum = red[0]; __syncthreads();
    float fwv[8];
    #pragma unroll
    for (int nn = 0; nn < 8; ++nn)
        fwv[nn] = ea[o0 + tx * 8 + nn] / esum;

    // ---- main loop ----
    const int ar = t >> 1;       // 0..127 row within tile
    const int ac = t & 1;        // 0..1 (float4 within 8-k chunk)
    const bool arow_ok = (i0 + ar) < NN;
    const float* __restrict__ xrow = x + (size_t)(i0 + ar) * XSTRIDE + g * DG + ac * 4;
    const float* __restrict__ wrow = W + (size_t)(o0 + ar) * DG + ac * 4;

    unsigned long long acc2[8][4];
    #pragma unroll
    for (int m = 0; m < 8; ++m)
        #pragma unroll
        for (int p = 0; p < 4; ++p) acc2[m][p] = 0ull;

    // prologue: stage 0
    {
        float4 avec = make_float4(0.f, 0.f, 0.f, 0.f);
        if (arow_ok) avec = *(const float4*)xrow;
        float4 bvec = *(const float4*)wrow;
        As[0][ac * 4 + 0][ar] = avec.x; As[0][ac * 4 + 1][ar] = avec.y;
        As[0][ac * 4 + 2][ar] = avec.z; As[0][ac * 4 + 3][ar] = avec.w;
        Bs[0][ac * 4 + 0][ar] = bvec.x; Bs[0][ac * 4 + 1][ar] = bvec.y;
        Bs[0][ac * 4 + 2][ar] = bvec.z; Bs[0][ac * 4 + 3][ar] = bvec.w;
    }
    __syncthreads();

    int buf = 0;
    for (int k0 = 0; k0 < DG; k0 += BK) {
        const bool has_next = (k0 + BK) < DG;
        float4 avec = make_float4(0.f, 0.f, 0.f, 0.f), bvec;
        if (has_next) {
            if (arow_ok) avec = *(const float4*)(xrow + k0 + BK);
            bvec = *(const float4*)(wrow + k0 + BK);
        }

        #pragma unroll
        for (int k = 0; k < BK; ++k) {
            float4 a0  = *(const float4*)&As[buf][k][ty * 8];
            float4 a1v = *(const float4*)&As[buf][k][ty * 8 + 4];
            ulonglong2 b01 = *(const ulonglong2*)&Bs[buf][k][tx * 8];
            ulonglong2 b23 = *(const ulonglong2*)&Bs[buf][k][tx * 8 + 4];
            unsigned long long rb[4] = {b01.x, b01.y, b23.x, b23.y};
            float ra[8] = {a0.x, a0.y, a0.z, a0.w, a1v.x, a1v.y, a1v.z, a1v.w};
            #pragma unroll
            for (int m = 0; m < 8; ++m) {
                unsigned long long am = pack2(ra[m]);
                #pragma unroll
                for (int p = 0; p < 4; ++p)
                    ffma2(acc2[m][p], am, rb[p]);
            }
        }

        if (has_next) {
            int nb = buf ^ 1;
            As[nb][ac * 4 + 0][ar] = avec.x; As[nb][ac * 4 + 1][ar] = avec.y;
            As[nb][ac * 4 + 2][ar] = avec.z; As[nb][ac * 4 + 3][ar] = avec.w;
            Bs[nb][ac * 4 + 0][ar] = bvec.x; Bs[nb][ac * 4 + 1][ar] = bvec.y;
            Bs[nb][ac * 4 + 2][ar] = bvec.z; Bs[nb][ac * 4 + 3][ar] = bvec.w;
        }
        __syncthreads();
        buf ^= 1;
    }

    // ---- epilogue: unpack, scale by fw, clip, store ----
    #pragma unroll
    for (int m = 0; m < 8; ++m) {
        int gi = i0 + ty * 8 + m;
        if (gi >= NN) continue;
        float2 c0 = unpack2(acc2[m][0]);
        float2 c1 = unpack2(acc2[m][1]);
        float2 c2 = unpack2(acc2[m][2]);
        float2 c3 = unpack2(acc2[m][3]);
        float4 v0, v1;
        v0.x = fminf(1.f, fmaxf(-1.f, c0.x * fwv[0]));
        v0.y = fminf(1.f, fmaxf(-1.f, c0.y * fwv[1]));
        v0.z = fminf(1.f, fmaxf(-1.f, c1.x * fwv[2]));
        v0.w = fminf(1.f, fmaxf(-1.f, c1.y * fwv[3]));
        v1.x = fminf(1.f, fmaxf(-1.f, c2.x * fwv[4]));
        v1.y = fminf(1.f, fmaxf(-1.f, c2.y * fwv[5]));
        v1.z = fminf(1.f, fmaxf(-1.f, c3.x * fwv[6]));
        v1.w = fminf(1.f, fmaxf(-1.f, c3.y * fwv[7]));
        float* dst = &g_h[(size_t)gi * XSTRIDE + g * DG + o0 + tx * 8];
        *(float4*)dst = v0;
        *(float4*)(dst + 4) = v1;
    }
}

// ---------------------------------------------------------------------------
// Attention: one block per (node, group), 256 threads, neighbors in registers.
// Gathers use __ldcg (L2-only; zero L1 reuse at 20MB table).
// ---------------------------------------------------------------------------
__global__ __launch_bounds__(256)
void attn_kernel(const int* __restrict__ graph, float* __restrict__ out) {
    const int i = blockIdx.x;
    const int g = blockIdx.y;

    __shared__ int   idxs[KNN];
    __shared__ float part[2 * KNN];
    __shared__ float score[KNN];
    __shared__ float4 agg[4][64];

    const int t = threadIdx.x;
    if (t < KNN) idxs[t] = __ldg(&graph[(size_t)i * KNN + t]);
    __syncthreads();

    const int q    = t & 63;
    const int jb   = t >> 6;
    const int w    = t >> 5;
    const int lane = t & 31;

    const float* __restrict__ base = g_h + g * DG + q * 4;
    float4 ov = __ldcg((const float4*)(base + (size_t)i * XSTRIDE));

    // gather 8 neighbor chunks into registers (MLP=8, L2-only path)
    float4 nbv[8];
    #pragma unroll
    for (int r = 0; r < 8; ++r)
        nbv[r] = __ldcg((const float4*)(base + (size_t)idxs[4 * r + jb] * XSTRIDE));

    // squared-distance partials -> warp reduce -> 2 partials per j
    #pragma unroll
    for (int r = 0; r < 8; ++r) {
        float dx = ov.x - nbv[r].x, dy = ov.y - nbv[r].y;
        float dz = ov.z - nbv[r].z, dw = ov.w - nbv[r].w;
        float s = dx * dx + dy * dy + dz * dz + dw * dw;
        #pragma unroll
        for (int off = 16; off; off >>= 1) s += __shfl_xor_sync(0xffffffffu, s, off);
        if (lane == 0) part[(4 * r + jb) * 2 + (w & 1)] = s;
    }
    __syncthreads();

    // softmax over 32 scores (warp 0)
    if (t < KNN) {
        float s = -(part[2 * t] + part[2 * t + 1]);
        float m = s;
        #pragma unroll
        for (int off = 16; off; off >>= 1) m = fmaxf(m, __shfl_xor_sync(0xffffffffu, m, off));
        float e = __expf(s - m);
        float sum = e;
        #pragma unroll
        for (int off = 16; off; off >>= 1) sum += __shfl_xor_sync(0xffffffffu, sum, off);
        score[t] = e / sum;
    }
    __syncthreads();

    // weighted aggregate from registers
    float4 acc = make_float4(0.f, 0.f, 0.f, 0.f);
    #pragma unroll
    for (int r = 0; r < 8; ++r) {
        float wt = score[4 * r + jb];
        acc.x = fmaf(wt, nbv[r].x, acc.x);
        acc.y = fmaf(wt, nbv[r].y, acc.y);
        acc.z = fmaf(wt, nbv[r].z, acc.z);
        acc.w = fmaf(wt, nbv[r].w, acc.w);
    }
    agg[jb][q] = acc;
    __syncthreads();

    // final cross-thread reduce + store
    if (t < 64) {
        float4 s0 = agg[0][t], s1 = agg[1][t], s2 = agg[2][t], s3 = agg[3][t];
        float4 o;
        o.x = (s0.x + s1.x) + (s2.x + s3.x);
        o.y = (s0.y + s1.y) + (s2.y + s3.y);
        o.z = (s0.z + s1.z) + (s2.z + s3.z);
        o.w = (s0.w + s1.w) + (s2.w + s3.w);
        *(float4*)&out[(size_t)i * XSTRIDE + g * DG + t * 4] = o;
    }
}

// ---------------------------------------------------------------------------
// Launch
// ---------------------------------------------------------------------------
extern "C" void kernel_launch(void* const* d_in, const int* in_sizes, int n_in,
                              void* d_out, int out_size) {
    const float* x     = (const float*)d_in[0];
    const float* W1    = (const float*)d_in[1];
    const float* a1    = (const float*)d_in[2];
    const float* W2    = (const float*)d_in[3];
    const float* a2    = (const float*)d_in[4];
    const int*   graph = (const int*)d_in[5];
    float* out = (float*)d_out;

    dim3 ggrid((NN + BM - 1) / BM, ODIM / BN, 2);
    gemm_kernel<<<ggrid, 256>>>(x, W1, a1, W2, a2);

    dim3 agrid(NN, 2);
    attn_kernel<<<agrid, 256>>>(graph, out);
}